// round 17
// baseline (speedup 1.0000x reference)
#include <cuda_runtime.h>
#include <cuda_bf16.h>
#include <math.h>

// Problem constants
#define CB 2
#define CS 2048
#define CHID 1024
#define CH 8
#define CKV 4
#define CD 128
#define CBS (CB * CS)                 // 4096 rows
#define CSCALE 0.08838834764831845f   // 128^-0.5

// Scratch (allocation-free rule: __device__ globals)
__device__ float g_q[CBS * CH * CD];      // raw fp32 (rope+round fused into attn)
__device__ float g_k[CBS * CKV * CD];     // raw fp32 (ropek ropes+rounds)
__device__ float g_v[CBS * CKV * CD];     // tf32-RNA rounded at qkv epilogue
__device__ float g_biasT[CH * CB * CS];   // dyn transposed: [h][b][s]
__device__ float g_attn[CBS * CH * CD];   // attention output (fp32)

__device__ __forceinline__ void cp16(unsigned dst, const void* src) {
    asm volatile("cp.async.cg.shared.global [%0], [%1], 16;\n" :: "r"(dst), "l"(src));
}

__device__ __forceinline__ unsigned f2tf32(float x) {
    unsigned r;
    asm("cvt.rna.tf32.f32 %0, %1;\n" : "=r"(r) : "f"(x));
    return r;
}
__device__ __forceinline__ float tf32r(float x) { return __uint_as_float(f2tf32(x)); }

__device__ __forceinline__ void mma_tf32(float* d, const unsigned* a, const unsigned* b) {
    asm volatile(
        "mma.sync.aligned.m16n8k8.row.col.f32.tf32.tf32.f32 "
        "{%0,%1,%2,%3}, {%4,%5,%6,%7}, {%8,%9}, {%0,%1,%2,%3};\n"
        : "+f"(d[0]), "+f"(d[1]), "+f"(d[2]), "+f"(d[3])
        : "r"(a[0]), "r"(a[1]), "r"(a[2]), "r"(a[3]), "r"(b[0]), "r"(b[1]));
}

// ===========================================================================
// SINGLE-PASS tf32 GEMM: C[128,128] = A[128,1024] @ B[1024,128].
// Raw fp32 staged; operands RNA-rounded to tf32 in-register after LDS.
// Exact over rounded inputs. A pad 36, B pad 132 (conflict-free frags).
// Used for BOTH the qkv projection and the output projection.
// ===========================================================================
#define QAS_OFF 0
#define QBS_OFF (2 * 4608)                       // 9216
#define QKV_SMEM_FLOATS (QBS_OFF + 2 * 4224)     // 17664
#define QKV_SMEM_BYTES (QKV_SMEM_FLOATS * 4)     // 70656

__device__ __forceinline__ void gemm128_tf32_1p(
    const float* __restrict__ A, int lda,
    const float* __restrict__ B, int ldb,
    float* __restrict__ C, int ldc, bool roundC)
{
    extern __shared__ float smf[];
    const unsigned smBase = (unsigned)__cvta_generic_to_shared(smf);

    const int tid = threadIdx.x;
    const int w = tid >> 5, lane = tid & 31;
    const int g = lane >> 2, t = lane & 3;
    const int rb = (w >> 2) * 64;
    const int cb = (w & 3) * 32;

    float acc[4][4][4];
#pragma unroll
    for (int mt = 0; mt < 4; ++mt)
#pragma unroll
        for (int nt = 0; nt < 4; ++nt)
#pragma unroll
            for (int r = 0; r < 4; ++r) acc[mt][nt][r] = 0.f;

    auto issue = [&](int k0, int s) {
#pragma unroll
        for (int i = 0; i < 4; ++i) {
            const int idx = tid + i * 256;
            const int r = idx >> 3, c = (idx & 7) << 2;
            cp16(smBase + (unsigned)((QAS_OFF + s * 4608 + r * 36 + c) << 2),
                 A + (size_t)r * lda + k0 + c);
        }
#pragma unroll
        for (int i = 0; i < 4; ++i) {
            const int idx = tid + i * 256;
            const int r = idx >> 5, c = (idx & 31) << 2;
            cp16(smBase + (unsigned)((QBS_OFF + s * 4224 + r * 132 + c) << 2),
                 B + (size_t)(k0 + r) * ldb + c);
        }
        asm volatile("cp.async.commit_group;\n");
    };

    issue(0, 0);
    int s = 0;
    for (int k0 = 0; k0 < 1024; k0 += 32) {
        asm volatile("cp.async.wait_group 0;\n");
        __syncthreads();
        if (k0 + 32 < 1024) issue(k0 + 32, s ^ 1);
        const float* AsS = smf + QAS_OFF + s * 4608;
        const float* BsS = smf + QBS_OFF + s * 4224;
#pragma unroll
        for (int ks = 0; ks < 4; ++ks) {
            const int kk = ks * 8;
            unsigned af[4][4], bf[4][2];
#pragma unroll
            for (int mt = 0; mt < 4; ++mt) {
                const float* p = AsS + (rb + mt * 16 + g) * 36 + kk + t;
                af[mt][0] = f2tf32(p[0]);
                af[mt][1] = f2tf32(p[8 * 36]);
                af[mt][2] = f2tf32(p[4]);
                af[mt][3] = f2tf32(p[8 * 36 + 4]);
            }
#pragma unroll
            for (int nt = 0; nt < 4; ++nt) {
                const float* p = BsS + (kk + t) * 132 + cb + nt * 8 + g;
                bf[nt][0] = f2tf32(p[0]);
                bf[nt][1] = f2tf32(p[4 * 132]);
            }
#pragma unroll
            for (int mt = 0; mt < 4; ++mt)
#pragma unroll
                for (int nt = 0; nt < 4; ++nt)
                    mma_tf32(acc[mt][nt], af[mt], bf[nt]);
        }
        s ^= 1;
    }

#pragma unroll
    for (int mt = 0; mt < 4; ++mt)
#pragma unroll
        for (int nt = 0; nt < 4; ++nt) {
            const int r0 = rb + mt * 16 + g;
            const int c0 = cb + nt * 8 + 2 * t;
            float v0 = acc[mt][nt][0], v1 = acc[mt][nt][1];
            float v2 = acc[mt][nt][2], v3 = acc[mt][nt][3];
            if (roundC) { v0 = tf32r(v0); v1 = tf32r(v1); v2 = tf32r(v2); v3 = tf32r(v3); }
            *(float2*)(C + (size_t)r0 * ldc + c0)       = make_float2(v0, v1);
            *(float2*)(C + (size_t)(r0 + 8) * ldc + c0) = make_float2(v2, v3);
        }
}

// Kernel 1: fused QKV projection, single-pass tf32; V output rounded to tf32
__global__ void __launch_bounds__(256, 2) k_qkv_tc(
    const float* __restrict__ hidden,
    const float* __restrict__ Wq,
    const float* __restrict__ Wk,
    const float* __restrict__ Wv)
{
    const int n0 = blockIdx.x * 128;
    const int m0 = blockIdx.y * 128;
    const float* A = hidden + (size_t)m0 * CHID;
    if (n0 < 1024)
        gemm128_tf32_1p(A, CHID, Wq + n0, 1024, g_q + (size_t)m0 * 1024 + n0, 1024, false);
    else if (n0 < 1536)
        gemm128_tf32_1p(A, CHID, Wk + (n0 - 1024), 512, g_k + (size_t)m0 * 512 + (n0 - 1024), 512, false);
    else
        gemm128_tf32_1p(A, CHID, Wv + (n0 - 1536), 512, g_v + (size_t)m0 * 512 + (n0 - 1536), 512, true);
}

// Kernel 5: output projection, single-pass tf32 (same validated transform)
__global__ void __launch_bounds__(256, 2) k_out_tc(
    const float* __restrict__ Wo, float* __restrict__ out)
{
    const int n0 = blockIdx.x * 128;
    const int m0 = blockIdx.y * 128;
    gemm128_tf32_1p(g_attn + (size_t)m0 * 1024, 1024, Wo + n0, 1024,
                    out + (size_t)m0 * 1024 + n0, 1024, false);
}

// ---------------------------------------------------------------------------
// Kernel 2: RoPE on K ONLY; writes tf32-RNA-rounded values (QK exactness)
// ---------------------------------------------------------------------------
__global__ void k_ropek(const float* __restrict__ cosb, const float* __restrict__ sinb)
{
    const int t = blockIdx.x * blockDim.x + threadIdx.x;
    const int total = CBS * CKV * 64;
    if (t >= total) return;
    const int d = t & 63;
    const int head = (t >> 6) & 3;
    const int row = t >> 8;
    const int s = row & (CS - 1);
    const float c1  = cosb[s * CD + d];
    const float sn1 = sinb[s * CD + d];
    const float c2  = cosb[s * CD + d + 64];
    const float sn2 = sinb[s * CD + d + 64];
    float* p = g_k + (size_t)row * (CKV * CD) + head * CD;
    const float x1 = p[d], x2 = p[d + 64];
    p[d]      = tf32r(x1 * c1 - x2 * sn1);
    p[d + 64] = tf32r(x2 * c2 + x1 * sn2);
}

// ---------------------------------------------------------------------------
// Kernel 3: dt = v_flat @ Wdt ; dyn = exp(A * softplus(dt)) -> g_biasT [h][b][s]
// W staged TRANSPOSED with stride 516: reads sWT[h*516+j] are conflict-free
// (lane-consecutive j), fill banks j+4h distinct across h.
// ---------------------------------------------------------------------------
__global__ void __launch_bounds__(256) k_biask(
    const float* __restrict__ Wdt, const float* __restrict__ Aw)
{
    __shared__ float sWT[8 * 516];
    for (int i = threadIdx.x; i < 4096; i += 256) {
        const int h = i & 7, j = i >> 3;      // Wdt[j*8+h] = Wdt[i] (coalesced)
        sWT[h * 516 + j] = Wdt[i];
    }
    __syncthreads();
    const int warp = threadIdx.x >> 5;
    const int lane = threadIdx.x & 31;
    const int row = blockIdx.x * 8 + warp;
    const float* vrow = g_v + (size_t)row * 512;
    float acc[8];
#pragma unroll
    for (int h = 0; h < 8; ++h) acc[h] = 0.f;
    for (int j = lane; j < 512; j += 32) {
        const float vv = vrow[j];
#pragma unroll
        for (int h = 0; h < 8; ++h) acc[h] = fmaf(vv, sWT[h * 516 + j], acc[h]);
    }
#pragma unroll
    for (int off = 16; off > 0; off >>= 1)
#pragma unroll
        for (int h = 0; h < 8; ++h)
            acc[h] += __shfl_xor_sync(0xffffffffu, acc[h], off);
    if (lane < 8) {
        const float dt = acc[lane];
        const float sp = (dt > 20.f) ? dt : log1pf(expf(dt));
        const int b = row >> 11;
        const int s = row & (CS - 1);
        g_biasT[(size_t)(lane * CB + b) * CS + s] = expf(Aw[lane] * sp);
    }
}

// ===========================================================================
// Kernel 4: causal flash attention, tf32 mma (Q rope fused; fp32 epilogue)
// ===========================================================================
#define KSTR 132
#define VSTR 136
#define PST 68
#define AT_KS 0
#define AT_VS (2 * 64 * KSTR)
#define AT_PS (AT_VS + 2 * 64 * VSTR)
#define AT_BIAS (AT_PS + 128 * PST)
#define ATTN_TC_FLOATS (AT_BIAS + 2 * 64)
#define ATTN_TC_BYTES (ATTN_TC_FLOATS * 4)

__global__ void __launch_bounds__(256, 1) k_attn_tc(
    const float* __restrict__ cosb, const float* __restrict__ sinb)
{
    extern __shared__ float sm[];
    float* Ks = sm + AT_KS;
    float* Vs = sm + AT_VS;
    float* Ps = sm + AT_PS;
    float* bias_s = sm + AT_BIAS;
    const unsigned smBase = (unsigned)__cvta_generic_to_shared(sm);

    const int tid = threadIdx.x;
    const int w = tid >> 5, lane = tid & 31;
    const int g = lane >> 2, t = lane & 3;
    const int bh = blockIdx.x;
    const int b = bh >> 3;
    const int h = bh & 7;
    const int kvh = h >> 1;
    const int qt = (int)gridDim.y - 1 - (int)blockIdx.y;
    const int q0 = qt * 128;
    const int qw = w * 16;
    const int qg0 = q0 + qw + g;
    const int qg1 = qg0 + 8;

    // Q fragments: load raw fp32 q, apply RoPE in-register, round to tf32.
    unsigned aq[16][4];
    {
        const float* qp = g_q + (size_t)(b * CS + qg0) * 1024 + h * 128;
#pragma unroll
        for (int kf = 0; kf < 16; ++kf) {
            aq[kf][0] = __float_as_uint(qp[kf * 8 + t]);
            aq[kf][1] = __float_as_uint(qp[8 * 1024 + kf * 8 + t]);
            aq[kf][2] = __float_as_uint(qp[kf * 8 + t + 4]);
            aq[kf][3] = __float_as_uint(qp[8 * 1024 + kf * 8 + t + 4]);
        }
#pragma unroll
        for (int kf = 0; kf < 8; ++kf) {
#pragma unroll
            for (int r = 0; r < 4; ++r) {
                const int d = kf * 8 + t + ((r >= 2) ? 4 : 0);
                const int s = (r & 1) ? qg1 : qg0;
                const float c1  = cosb[s * CD + d];
                const float sn1 = sinb[s * CD + d];
                const float c2  = cosb[s * CD + d + 64];
                const float sn2 = sinb[s * CD + d + 64];
                const float x1 = __uint_as_float(aq[kf][r]);
                const float x2 = __uint_as_float(aq[kf + 8][r]);
                aq[kf][r]     = f2tf32(x1 * c1 - x2 * sn1);
                aq[kf + 8][r] = f2tf32(x2 * c2 + x1 * sn2);
            }
        }
    }

    float O[16][4];
#pragma unroll
    for (int nt = 0; nt < 16; ++nt)
#pragma unroll
        for (int r = 0; r < 4; ++r) O[nt][r] = 0.f;
    float m0 = -1e30f, m1 = -1e30f, l0 = 0.f, l1 = 0.f;

    const int nkt = 2 * qt + 2;

    auto issue = [&](int kt, int st) {
        const int kbase = kt * 64;
#pragma unroll
        for (int i = 0; i < 8; ++i) {
            const int idx = tid + i * 256;
            const int c = idx >> 5, dc = (idx & 31) << 2;
            const size_t grow = (size_t)(b * CS + kbase + c) * 512 + kvh * 128 + dc;
            cp16(smBase + (unsigned)((AT_KS + st * 64 * KSTR + c * KSTR + dc) << 2), g_k + grow);
            cp16(smBase + (unsigned)((AT_VS + st * 64 * VSTR + c * VSTR + dc) << 2), g_v + grow);
        }
        if (tid < 16)
            cp16(smBase + (unsigned)((AT_BIAS + st * 64 + tid * 4) << 2),
                 g_biasT + (size_t)(h * CB + b) * CS + kbase + tid * 4);
        asm volatile("cp.async.commit_group;\n");
    };

    issue(0, 0);
    int st = 0;
    for (int kt = 0; kt < nkt; ++kt) {
        const int kbase = kt * 64;
        asm volatile("cp.async.wait_group 0;\n");
        __syncthreads();
        if (kt + 1 < nkt) issue(kt + 1, st ^ 1);

        const float* KsS = Ks + st * 64 * KSTR;
        const float* VsS = Vs + st * 64 * VSTR;
        const float* biasS = bias_s + st * 64;

        float sacc[8][4];
#pragma unroll
        for (int nt = 0; nt < 8; ++nt)
#pragma unroll
            for (int r = 0; r < 4; ++r) sacc[nt][r] = 0.f;
#pragma unroll
        for (int kf = 0; kf < 16; ++kf) {
#pragma unroll
            for (int nt = 0; nt < 8; ++nt) {
                unsigned bf[2];
                const float* kp = KsS + (nt * 8 + g) * KSTR + kf * 8 + t;
                bf[0] = __float_as_uint(kp[0]);
                bf[1] = __float_as_uint(kp[4]);
                mma_tf32(sacc[nt], aq[kf], bf);
            }
        }

        float mx0 = -1e30f, mx1 = -1e30f;
#pragma unroll
        for (int nt = 0; nt < 8; ++nt) {
            const int kg = kbase + nt * 8 + 2 * t;
            const float b0 = biasS[nt * 8 + 2 * t];
            const float b1 = biasS[nt * 8 + 2 * t + 1];
            sacc[nt][0] = (kg     <= qg0) ? fmaf(sacc[nt][0], CSCALE, b0) : -1e30f;
            sacc[nt][1] = (kg + 1 <= qg0) ? fmaf(sacc[nt][1], CSCALE, b1) : -1e30f;
            sacc[nt][2] = (kg     <= qg1) ? fmaf(sacc[nt][2], CSCALE, b0) : -1e30f;
            sacc[nt][3] = (kg + 1 <= qg1) ? fmaf(sacc[nt][3], CSCALE, b1) : -1e30f;
            mx0 = fmaxf(mx0, fmaxf(sacc[nt][0], sacc[nt][1]));
            mx1 = fmaxf(mx1, fmaxf(sacc[nt][2], sacc[nt][3]));
        }
        mx0 = fmaxf(mx0, __shfl_xor_sync(0xffffffffu, mx0, 1));
        mx0 = fmaxf(mx0, __shfl_xor_sync(0xffffffffu, mx0, 2));
        mx1 = fmaxf(mx1, __shfl_xor_sync(0xffffffffu, mx1, 1));
        mx1 = fmaxf(mx1, __shfl_xor_sync(0xffffffffu, mx1, 2));

        const float mn0 = fmaxf(m0, mx0);
        const float mn1 = fmaxf(m1, mx1);
        const float alpha0 = __expf(m0 - mn0);
        const float alpha1 = __expf(m1 - mn1);
        float sum0 = 0.f, sum1 = 0.f;
#pragma unroll
        for (int nt = 0; nt < 8; ++nt) {
            const float p0 = tf32r(__expf(sacc[nt][0] - mn0));
            const float p1 = tf32r(__expf(sacc[nt][1] - mn0));
            const float p2 = tf32r(__expf(sacc[nt][2] - mn1));
            const float p3 = tf32r(__expf(sacc[nt][3] - mn1));
            sum0 += p0 + p1;
            sum1 += p2 + p3;
            *(float2*)&Ps[(qw + g) * PST + nt * 8 + 2 * t]     = make_float2(p0, p1);
            *(float2*)&Ps[(qw + g + 8) * PST + nt * 8 + 2 * t] = make_float2(p2, p3);
        }
        sum0 += __shfl_xor_sync(0xffffffffu, sum0, 1);
        sum0 += __shfl_xor_sync(0xffffffffu, sum0, 2);
        sum1 += __shfl_xor_sync(0xffffffffu, sum1, 1);
        sum1 += __shfl_xor_sync(0xffffffffu, sum1, 2);
        l0 = l0 * alpha0 + sum0;  m0 = mn0;
        l1 = l1 * alpha1 + sum1;  m1 = mn1;

#pragma unroll
        for (int nt = 0; nt < 16; ++nt) {
            O[nt][0] *= alpha0; O[nt][1] *= alpha0;
            O[nt][2] *= alpha1; O[nt][3] *= alpha1;
        }

        __syncwarp();
#pragma unroll
        for (int kf = 0; kf < 8; ++kf) {
            unsigned ap[4];
            const float* pp = Ps + (qw + g) * PST + kf * 8 + t;
            ap[0] = __float_as_uint(pp[0]);
            ap[1] = __float_as_uint(pp[8 * PST]);
            ap[2] = __float_as_uint(pp[4]);
            ap[3] = __float_as_uint(pp[8 * PST + 4]);
#pragma unroll
            for (int nt = 0; nt < 16; ++nt) {
                unsigned bf[2];
                const float* vp = VsS + (kf * 8 + t) * VSTR + nt * 8 + g;
                bf[0] = __float_as_uint(vp[0]);
                bf[1] = __float_as_uint(vp[4 * VSTR]);
                mma_tf32(O[nt], ap, bf);
            }
        }
        __syncthreads();
        st ^= 1;
    }

    // epilogue: normalize; write plain fp32 for the single-pass tf32 k_out
    const float inv0 = 1.f / l0;
    const float inv1 = 1.f / l1;
    float* op0 = g_attn + (size_t)(b * CS + qg0) * 1024 + h * 128;
    float* op1 = g_attn + (size_t)(b * CS + qg1) * 1024 + h * 128;
#pragma unroll
    for (int nt = 0; nt < 16; ++nt) {
        *(float2*)(op0 + nt * 8 + 2 * t) = make_float2(O[nt][0] * inv0, O[nt][1] * inv0);
        *(float2*)(op1 + nt * 8 + 2 * t) = make_float2(O[nt][2] * inv1, O[nt][3] * inv1);
    }
}

// ---------------------------------------------------------------------------
extern "C" void kernel_launch(void* const* d_in, const int* in_sizes, int n_in,
                              void* d_out, int out_size)
{
    const float* hidden = (const float*)d_in[0];
    const float* Wq     = (const float*)d_in[1];
    const float* Wk     = (const float*)d_in[2];
    const float* Wv     = (const float*)d_in[3];
    const float* Wdt    = (const float*)d_in[4];
    const float* Aw     = (const float*)d_in[5];
    const float* Wo     = (const float*)d_in[6];
    const float* cosb   = (const float*)d_in[7];
    const float* sinb   = (const float*)d_in[8];
    float* out = (float*)d_out;

    cudaFuncSetAttribute(k_qkv_tc,  cudaFuncAttributeMaxDynamicSharedMemorySize, QKV_SMEM_BYTES);
    cudaFuncSetAttribute(k_out_tc,  cudaFuncAttributeMaxDynamicSharedMemorySize, QKV_SMEM_BYTES);
    cudaFuncSetAttribute(k_attn_tc, cudaFuncAttributeMaxDynamicSharedMemorySize, ATTN_TC_BYTES);

    k_qkv_tc<<<dim3(16, 32), 256, QKV_SMEM_BYTES>>>(hidden, Wq, Wk, Wv);
    k_ropek<<<(CBS * CKV * 64 + 255) / 256, 256>>>(cosb, sinb);
    k_biask<<<CBS / 8, 256>>>(Wdt, Aw);
    k_attn_tc<<<dim3(16, 16), 256, ATTN_TC_BYTES>>>(cosb, sinb);
    k_out_tc<<<dim3(8, 32), 256, QKV_SMEM_BYTES>>>(Wo, out);
}